// round 9
// baseline (speedup 1.0000x reference)
#include <cuda_runtime.h>
#include <math.h>
#include <stdint.h>

#define N_SLOTS 16384
#define MD      512
#define CTRL    1024
#define OUTF    (3*MD + 6)   // 1542
#define EPSF    1e-16f
#define NBLK    148
#define NWARP   8
#define GWARPS  (NBLK*NWARP)   // 1184

// ---- scratch (device globals: no allocation allowed) ----
__device__ float g_o[MD + 6];
__device__ float g_e[MD];
__device__ float g_a[MD];
__device__ float g_expwc[N_SLOTS];
__device__ float g_partialB[192];   // 148 used; tail stays zero forever
__device__ float g_partialC[192];
__device__ unsigned g_cnt2[2];      // barrier counters (self-resetting)
__device__ volatile unsigned g_gen; // barrier generation (monotonic across replays)

__device__ __forceinline__ float softplusf(float x) {
    return x > 20.f ? x : log1pf(expf(x));
}

// Grid barrier: alternating counters (idx&1) so a counter is only reset by the
// releaser of barrier i and next touched after barrier i+1 completes -> no race.
// gen is monotonic: works unchanged across graph replays, no reset needed.
__device__ __forceinline__ void grid_bar(int idx) {
    __syncthreads();
    if (threadIdx.x == 0) {
        unsigned my = g_gen;
        __threadfence();
        if (atomicAdd(&g_cnt2[idx & 1], 1u) == NBLK - 1u) {
            g_cnt2[idx & 1] = 0u;
            __threadfence();
            g_gen = my + 1u;
        } else {
            while (g_gen == my) { }
        }
        __threadfence();
    }
    __syncthreads();
}

__device__ __forceinline__ void mbar_wait0(uint32_t mbar) {
    unsigned done = 0;
    while (!done) {
        asm volatile(
            "{\n\t.reg .pred p;\n\t"
            "mbarrier.try_wait.parity.shared.b64 p, [%1], %2;\n\t"
            "selp.b32 %0, 1, 0, p;\n\t}"
            : "=r"(done) : "r"(mbar), "r"(0u) : "memory");
    }
}

extern __shared__ float4 s_mem[];   // nr rows x 128 float4 (<= 227,328 B)

__global__ void __launch_bounds__(256, 1)
k_fused(const float* __restrict__ emb, const float* __restrict__ w_prev,
        const float* __restrict__ mem, const float* __restrict__ W,
        const float* __restrict__ b, float* __restrict__ out)
{
    __shared__ float sk[MD];       // k vector; reused for wp in later phases
    __shared__ float s_red[128];
    __shared__ float sc[8];        // ise,g,s0,s1,s2,gamma,knorm,beta
    __shared__ __align__(8) uint64_t s_mbar;

    int tid = threadIdx.x, lane = tid & 31, wid = tid >> 5;
    int bid = blockIdx.x;
    int r0 = bid * 110 + (bid < 104 ? bid : 104);   // 104 blocks x111 + 44 x110 = 16384
    int nr = (bid < 104) ? 111 : 110;

    uint32_t mbar = (uint32_t)__cvta_generic_to_shared(&s_mbar);
    uint32_t sdst = (uint32_t)__cvta_generic_to_shared(s_mem);

    // ---- issue bulk copy of this block's memory slice (async, overlaps proj) ----
    if (tid == 0) {
        asm volatile("mbarrier.init.shared.b64 [%0], %1;" :: "r"(mbar), "r"(1u));
    }
    __syncthreads();
    if (tid == 0) {
        asm volatile("fence.proxy.async.shared::cta;" ::: "memory");
        unsigned total = (unsigned)nr * 2048u;
        asm volatile("mbarrier.arrive.expect_tx.shared.b64 _, [%0], %1;"
                     :: "r"(mbar), "r"(total) : "memory");
        const char* src = (const char*)(mem + (size_t)r0 * MD);
        for (int off = 0; off < nr; off += 32) {
            unsigned rows  = (unsigned)((nr - off < 32) ? (nr - off) : 32);
            unsigned bytes = rows * 2048u;
            asm volatile(
                "cp.async.bulk.shared::cluster.global.mbarrier::complete_tx::bytes "
                "[%0], [%1], %2, [%3];"
                :: "r"(sdst + (unsigned)off * 2048u), "l"(src + (size_t)off * 2048u),
                   "r"(bytes), "r"(mbar) : "memory");
        }
    }

    // ---- Phase P: o = emb @ W^T + b (one warp per row; overlaps the TMA read) ----
    for (int j = 0; j < 2; j++) {
        int row = bid * NWARP + wid + j * GWARPS;
        if (row < OUTF) {
            const float4* W4  = (const float4*)(W + (size_t)row * CTRL);
            const float4* eb4 = (const float4*)emb;
            float sum = 0.f;
#pragma unroll
            for (int q = 0; q < 8; q++) {
                float4 wv = W4[lane + 32*q];
                float4 evv = eb4[lane + 32*q];
                sum += wv.x*evv.x + wv.y*evv.y + wv.z*evv.z + wv.w*evv.w;
            }
#pragma unroll
            for (int off = 16; off; off >>= 1) sum += __shfl_down_sync(0xffffffffu, sum, off);
            if (lane == 0) {
                float o = sum + b[row];
                if (row < MD + 6)          g_o[row] = o;
                else if (row < 2*MD + 6)   g_e[row - (MD + 6)] = o;
                else                       g_a[row - (2*MD + 6)] = o;
            }
        }
    }
    grid_bar(0);   // g_o / g_e / g_a complete

    // ---- Phase S: cosine sim + exp(beta*sim) from SMEM-resident rows ----
    float ksq = 0.f;
#pragma unroll
    for (int i = tid; i < MD; i += 256) { float v = g_o[i]; sk[i] = v; ksq += v*v; }
#pragma unroll
    for (int off = 16; off; off >>= 1) ksq += __shfl_down_sync(0xffffffffu, ksq, off);
    if (lane == 0) s_red[wid] = ksq;
    __syncthreads();
    if (tid == 0) {
        float s = 0.f;
#pragma unroll
        for (int i = 0; i < 8; i++) s += s_red[i];
        sc[6] = sqrtf(s);
        sc[7] = softplusf(g_o[MD]);
    }
    __syncthreads();
    float s_knorm = sc[6], s_beta = sc[7];

    mbar_wait0(mbar);   // memory slice resident in SMEM

    float4 kv[4];
#pragma unroll
    for (int q = 0; q < 4; q++) kv[q] = ((const float4*)sk)[lane + 32*q];

    float wsum = 0.f;   // per-warp (lane0) fixed-order accumulation
    for (int lr = wid; lr < nr; lr += NWARP) {
        const float4* mr = s_mem + lr * 128;
        float dot = 0.f, nrm = 0.f;
#pragma unroll
        for (int q = 0; q < 4; q++) {
            float4 mv = mr[lane + 32*q];
            dot += mv.x*kv[q].x + mv.y*kv[q].y + mv.z*kv[q].z + mv.w*kv[q].w;
            nrm += mv.x*mv.x + mv.y*mv.y + mv.z*mv.z + mv.w*mv.w;
        }
#pragma unroll
        for (int off = 16; off; off >>= 1) {
            dot += __shfl_down_sync(0xffffffffu, dot, off);
            nrm += __shfl_down_sync(0xffffffffu, nrm, off);
        }
        if (lane == 0) {
            // sim in [-1,1], beta = softplus(~N(0,1)) modest: exp cannot overflow
            float ex = expf(s_beta * dot / (s_knorm * sqrtf(nrm) + EPSF));
            g_expwc[r0 + lr] = ex;
            wsum += ex;
        }
    }
    if (lane == 0) s_red[wid] = wsum;
    __syncthreads();
    if (tid == 0) {
        float s = 0.f;
#pragma unroll
        for (int i = 0; i < 8; i++) s += s_red[i];
        g_partialB[bid] = s;
    }
    grid_bar(1);   // all expwc + partials visible

    // ---- Phase F: scalars + interpolate/shift/sharpen for own slots ----
    if (wid == 0) {
        float s = g_partialB[lane] + g_partialB[lane+32] + g_partialB[lane+64]
                + g_partialB[lane+96] + g_partialB[lane+128];   // fixed order; pad=0
#pragma unroll
        for (int off = 16; off; off >>= 1) s += __shfl_xor_sync(0xffffffffu, s, off);
        if (lane == 0) {
            sc[0] = 1.f / s;
            sc[1] = 1.f / (1.f + expf(-g_o[MD+1]));
            float x0 = g_o[MD+2], x1 = g_o[MD+3], x2 = g_o[MD+4];
            float mx = fmaxf(x0, fmaxf(x1, x2));
            float e0 = expf(x0-mx), e1 = expf(x1-mx), e2 = expf(x2-mx);
            float invs = 1.f / (e0 + e1 + e2);
            sc[2] = e0*invs; sc[3] = e1*invs; sc[4] = e2*invs;
            sc[5] = 1.f + softplusf(g_o[MD+5]);
        }
    }
    __syncthreads();
    float ise = sc[0], gg = sc[1], sh0 = sc[2], sh1 = sc[3], sh2 = sc[4], gamma = sc[5];
    float omg = 1.f - gg;
    if (tid < nr) {
        int i  = r0 + tid;
        int im = (i == 0) ? N_SLOTS-1 : i-1;
        int ip = (i == N_SLOTS-1) ? 0 : i+1;
        float wgm = gg * g_expwc[im] * ise + omg * w_prev[im];
        float wgc = gg * g_expwc[i ] * ise + omg * w_prev[i ];
        float wgp = gg * g_expwc[ip] * ise + omg * w_prev[ip];
        float ws = sh0*wgm + sh1*wgc + sh2*wgp;
        sk[tid] = exp2f(gamma * log2f(ws + EPSF));   // ws+EPS > 0 always; sk now holds wp
    }
    __syncthreads();
    if (tid < 128) {
        float v = (tid       < nr ? sk[tid]       : 0.f)
                + (tid + 128 < nr ? sk[tid + 128] : 0.f);
        s_red[tid] = v;
    }
    __syncthreads();
    for (int st = 64; st; st >>= 1) { if (tid < st) s_red[tid] += s_red[tid+st]; __syncthreads(); }
    if (tid == 0) g_partialC[bid] = s_red[0];
    grid_bar(2);   // all wp partials visible

    // ---- Phase U: normalize + memory update straight from SMEM ----
    float s = g_partialC[lane] + g_partialC[lane+32] + g_partialC[lane+64]
            + g_partialC[lane+96] + g_partialC[lane+128];   // fixed order; pad=0
#pragma unroll
    for (int off = 16; off; off >>= 1) s += __shfl_xor_sync(0xffffffffu, s, off);
    float inv = 1.f / s;

    if (tid < nr) out[r0 + tid] = sk[tid] * inv;

    float4 ev[4], av[4];
#pragma unroll
    for (int q = 0; q < 4; q++) {
        ev[q] = ((const float4*)g_e)[lane + 32*q];
        av[q] = ((const float4*)g_a)[lane + 32*q];
    }
    float* nm = out + N_SLOTS;
    for (int lr = wid; lr < nr; lr += NWARP) {
        float wv = sk[lr] * inv;
        const float4* mr = s_mem + lr * 128;
        float4* o4 = (float4*)(nm + (size_t)(r0 + lr) * MD);
#pragma unroll
        for (int q = 0; q < 4; q++) {
            float4 m = mr[lane + 32*q];
            float4 r;
            r.x = m.x * (1.f - wv*ev[q].x) + wv*av[q].x;
            r.y = m.y * (1.f - wv*ev[q].y) + wv*av[q].y;
            r.z = m.z * (1.f - wv*ev[q].z) + wv*av[q].z;
            r.w = m.w * (1.f - wv*ev[q].w) + wv*av[q].w;
            __stcs(o4 + lane + 32*q, r);   // streaming: never re-read
        }
    }
}

extern "C" void kernel_launch(void* const* d_in, const int* in_sizes, int n_in,
                              void* d_out, int out_size) {
    const float* emb    = (const float*)d_in[0];   // (1, 1024)
    const float* w_prev = (const float*)d_in[1];   // (1, 16384)
    const float* mem    = (const float*)d_in[2];   // (16384, 512)
    const float* W      = (const float*)d_in[3];   // (1542, 1024)
    const float* b      = (const float*)d_in[4];   // (1542,)
    float* out = (float*)d_out;                    // [w(16384) | new_memory(16384*512)]

    const int smem_bytes = 111 * 2048;   // 227,328 B dynamic
    cudaFuncSetAttribute(k_fused, cudaFuncAttributeMaxDynamicSharedMemorySize, smem_bytes);
    k_fused<<<NBLK, 256, smem_bytes>>>(emb, w_prev, mem, W, b, out);
}

// round 10
// speedup vs baseline: 1.1635x; 1.1635x over previous
#include <cuda_runtime.h>
#include <math.h>
#include <stdint.h>

#define N_SLOTS 16384
#define MD      512
#define CTRL    1024
#define OUTF    (3*MD + 6)   // 1542
#define EPSF    1e-16f

// ---- scratch (device globals: no allocation allowed) ----
__device__ float g_o[MD + 6];     // k (512) + 6 scalars
__device__ float g_e[MD];
__device__ float g_a[MD];
__device__ float g_expwc[N_SLOTS];
__device__ float g_wp[N_SLOTS];
__device__ float g_partialB[1024];
__device__ float g_partialC[64];

__device__ __forceinline__ float softplusf(float x) {
    return x > 20.f ? x : log1pf(expf(x));
}

// ---- K1: o = emb @ W^T + b (one warp per output row).
//      Rows [0,518) -> g_o ; e rows -> g_e (aligned) ; a rows -> g_a. ----
__global__ void k_proj(const float* __restrict__ emb,
                       const float* __restrict__ W,
                       const float* __restrict__ b) {
    int warp = threadIdx.x >> 5;
    int lane = threadIdx.x & 31;
    int row  = blockIdx.x * 4 + warp;
    if (row >= OUTF) return;
    const float4* W4 = (const float4*)(W + (size_t)row * CTRL);
    const float4* e4 = (const float4*)emb;
    float sum = 0.f;
#pragma unroll
    for (int j = 0; j < 8; j++) {
        float4 wv = W4[lane + 32*j];
        float4 ev = e4[lane + 32*j];
        sum += wv.x*ev.x + wv.y*ev.y + wv.z*ev.z + wv.w*ev.w;
    }
#pragma unroll
    for (int off = 16; off; off >>= 1) sum += __shfl_down_sync(0xffffffffu, sum, off);
    if (lane == 0) {
        float o = sum + b[row];
        if (row < MD + 6)            g_o[row] = o;
        else if (row < 2*MD + 6)     g_e[row - (MD + 6)] = o;
        else                         g_a[row - (2*MD + 6)] = o;
    }
}

// ---- K2: cosine sim + exp(beta*sim). 2 rows per warp (8 outstanding
//      LDG.128/thread, front-batched). Block derives knorm/beta itself. ----
__global__ void k_sim(const float* __restrict__ mem) {
    __shared__ float sk[MD];
    __shared__ float sred[16];
    __shared__ float s_beta, s_knorm;
    int tid = threadIdx.x;
    int wid = tid >> 5, lane = tid & 31;

    // front-batch the 8 global row loads (independent of k/smem work)
    int row0 = blockIdx.x * 16 + wid;        // rows row0 and row0+8
    const float4* mA = (const float4*)(mem + (size_t)row0 * MD);
    const float4* mB = (const float4*)(mem + (size_t)(row0 + 8) * MD);
    float4 va[4], vb[4];
#pragma unroll
    for (int j = 0; j < 4; j++) va[j] = mA[lane + 32*j];
#pragma unroll
    for (int j = 0; j < 4; j++) vb[j] = mB[lane + 32*j];

    float ksq = 0.f;
#pragma unroll
    for (int i = tid; i < MD; i += 256) { float v = g_o[i]; sk[i] = v; ksq += v*v; }
#pragma unroll
    for (int off = 16; off; off >>= 1) ksq += __shfl_down_sync(0xffffffffu, ksq, off);
    if (lane == 0) sred[wid] = ksq;
    __syncthreads();
    if (tid == 0) {
        float s = 0.f;
#pragma unroll
        for (int i = 0; i < 8; i++) s += sred[i];
        s_knorm = sqrtf(s);
        s_beta  = softplusf(g_o[MD]);
    }
    __syncthreads();   // sk + s_beta/s_knorm ready

    const float4* k4 = (const float4*)sk;
    float dotA = 0.f, nrmA = 0.f, dotB = 0.f, nrmB = 0.f;
#pragma unroll
    for (int j = 0; j < 4; j++) {
        float4 kv = k4[lane + 32*j];
        dotA += va[j].x*kv.x + va[j].y*kv.y + va[j].z*kv.z + va[j].w*kv.w;
        nrmA += va[j].x*va[j].x + va[j].y*va[j].y + va[j].z*va[j].z + va[j].w*va[j].w;
        dotB += vb[j].x*kv.x + vb[j].y*kv.y + vb[j].z*kv.z + vb[j].w*kv.w;
        nrmB += vb[j].x*vb[j].x + vb[j].y*vb[j].y + vb[j].z*vb[j].z + vb[j].w*vb[j].w;
    }
#pragma unroll
    for (int off = 16; off; off >>= 1) {
        dotA += __shfl_down_sync(0xffffffffu, dotA, off);
        nrmA += __shfl_down_sync(0xffffffffu, nrmA, off);
        dotB += __shfl_down_sync(0xffffffffu, dotB, off);
        nrmB += __shfl_down_sync(0xffffffffu, nrmB, off);
    }
    if (lane == 0) {
        // sim in [-1,1], beta = softplus(~N(0,1)) modest: exp cannot overflow
        float exA = expf(s_beta * dotA / (s_knorm * sqrtf(nrmA) + EPSF));
        float exB = expf(s_beta * dotB / (s_knorm * sqrtf(nrmB) + EPSF));
        g_expwc[row0]     = exA;
        g_expwc[row0 + 8] = exB;
        sred[wid]     = exA;
        sred[wid + 8] = exB;
    }
    __syncthreads();
    if (tid == 0) {
        float s = 0.f;
#pragma unroll
        for (int i = 0; i < 16; i++) s += sred[i];
        g_partialB[blockIdx.x] = s;
    }
}

// ---- K3: interpolate + shift + sharpen. Each block redundantly reduces
//      the 1024 exp-partials and derives scalars. 64 blocks x 256. ----
__global__ void k_shiftpow(const float* __restrict__ w_prev) {
    __shared__ float red[256];
    __shared__ float sc[6];   // ise, g, s0, s1, s2, gamma
    int tid = threadIdx.x;

    float s = 0.f;
#pragma unroll
    for (int j = 0; j < 4; j++) s += g_partialB[tid + 256*j];
    red[tid] = s;
    __syncthreads();
    for (int st = 128; st; st >>= 1) { if (tid < st) red[tid] += red[tid+st]; __syncthreads(); }
    if (tid == 0) {
        sc[0] = 1.f / red[0];
        sc[1] = 1.f / (1.f + expf(-g_o[MD+1]));
        float x0 = g_o[MD+2], x1 = g_o[MD+3], x2 = g_o[MD+4];
        float m  = fmaxf(x0, fmaxf(x1, x2));
        float e0 = expf(x0-m), e1 = expf(x1-m), e2 = expf(x2-m);
        float inv = 1.f / (e0 + e1 + e2);
        sc[2] = e0*inv; sc[3] = e1*inv; sc[4] = e2*inv;
        sc[5] = 1.f + softplusf(g_o[MD+5]);
    }
    __syncthreads();

    float ise = sc[0], gg = sc[1], s0 = sc[2], s1 = sc[3], s2 = sc[4], gamma = sc[5];
    float omg = 1.f - gg;
    int i = blockIdx.x * 256 + tid;
    int im = (i == 0) ? N_SLOTS-1 : i-1;
    int ip = (i == N_SLOTS-1) ? 0 : i+1;
    float wgm = gg * g_expwc[im] * ise + omg * w_prev[im];
    float wgc = gg * g_expwc[i ] * ise + omg * w_prev[i ];
    float wgp = gg * g_expwc[ip] * ise + omg * w_prev[ip];
    float ws = s0*wgm + s1*wgc + s2*wgp;
    float wp = exp2f(gamma * log2f(ws + EPSF));   // ws+EPS > 0 always
    g_wp[i] = wp;
    red[tid] = wp;
    __syncthreads();
    for (int st = 128; st; st >>= 1) { if (tid < st) red[tid] += red[tid+st]; __syncthreads(); }
    if (tid == 0) g_partialC[blockIdx.x] = red[0];
}

// ---- K4: memory update. 16 rows per 256-thread block (2 rows/warp).
//      Results staged in SMEM, written by ONE 32KB TMA bulk store/block
//      (bypasses per-thread STG issue + L1tex store wavefront limits). ----
__global__ void __launch_bounds__(256)
k_update(const float* __restrict__ mem, float* __restrict__ out) {
    __shared__ __align__(16) float4 stage[16 * 128];   // 32 KB
    int tid  = threadIdx.x;
    int lane = tid & 31;
    int wid  = tid >> 5;
    int base = blockIdx.x * 16;

    // front-batch this warp's 2 row loads (8 independent LDG.128/thread)
    int rA = base + wid;        // rows base+wid and base+wid+8
    int rB = rA + 8;
    const float4* mA = (const float4*)(mem + (size_t)rA * MD);
    const float4* mB = (const float4*)(mem + (size_t)rB * MD);
    float4 va[4], vb[4];
#pragma unroll
    for (int q = 0; q < 4; q++) va[q] = mA[lane + 32*q];
#pragma unroll
    for (int q = 0; q < 4; q++) vb[q] = mB[lane + 32*q];

    // warp-redundant deterministic reduce of 64 wp-partials (no block barrier)
    float s = g_partialC[lane] + g_partialC[lane + 32];
#pragma unroll
    for (int off = 16; off; off >>= 1) s += __shfl_xor_sync(0xffffffffu, s, off);
    float inv = 1.f / s;

    float wA = g_wp[rA] * inv;
    float wB = g_wp[rB] * inv;
    if (tid < 16) out[base + tid] = g_wp[base + tid] * inv;

#pragma unroll
    for (int q = 0; q < 4; q++) {
        float4 e = ((const float4*)g_e)[lane + 32*q];
        float4 a = ((const float4*)g_a)[lane + 32*q];
        float4 r;
        r.x = va[q].x * (1.f - wA*e.x) + wA*a.x;
        r.y = va[q].y * (1.f - wA*e.y) + wA*a.y;
        r.z = va[q].z * (1.f - wA*e.z) + wA*a.z;
        r.w = va[q].w * (1.f - wA*e.w) + wA*a.w;
        stage[wid * 128 + lane + 32*q] = r;
        float4 r2;
        r2.x = vb[q].x * (1.f - wB*e.x) + wB*a.x;
        r2.y = vb[q].y * (1.f - wB*e.y) + wB*a.y;
        r2.z = vb[q].z * (1.f - wB*e.z) + wB*a.z;
        r2.w = vb[q].w * (1.f - wB*e.w) + wB*a.w;
        stage[(wid + 8) * 128 + lane + 32*q] = r2;
    }
    __syncthreads();

    if (tid == 0) {
        uint32_t saddr = (uint32_t)__cvta_generic_to_shared(stage);
        float* dst = out + N_SLOTS + (size_t)base * MD;
        asm volatile("fence.proxy.async.shared::cta;" ::: "memory");
        asm volatile(
            "cp.async.bulk.global.shared::cta.bulk_group [%0], [%1], %2;"
            :: "l"(dst), "r"(saddr), "r"(32768u) : "memory");
        asm volatile("cp.async.bulk.commit_group;" ::: "memory");
        asm volatile("cp.async.bulk.wait_group 0;" ::: "memory");
    }
}

extern "C" void kernel_launch(void* const* d_in, const int* in_sizes, int n_in,
                              void* d_out, int out_size) {
    const float* emb    = (const float*)d_in[0];   // (1, 1024)
    const float* w_prev = (const float*)d_in[1];   // (1, 16384)
    const float* mem    = (const float*)d_in[2];   // (16384, 512)
    const float* W      = (const float*)d_in[3];   // (1542, 1024)
    const float* b      = (const float*)d_in[4];   // (1542,)
    float* out = (float*)d_out;                    // [w(16384) | new_memory(16384*512)]

    k_proj<<<(OUTF + 3) / 4, 128>>>(emb, W, b);
    k_sim<<<N_SLOTS / 16, 256>>>(mem);
    k_shiftpow<<<N_SLOTS / 256, 256>>>(w_prev);
    k_update<<<N_SLOTS / 16, 256>>>(mem, out);
}

// round 11
// speedup vs baseline: 1.2904x; 1.1091x over previous
#include <cuda_runtime.h>
#include <math.h>
#include <stdint.h>

#define N_SLOTS 16384
#define MD      512
#define CTRL    1024
#define OUTF    (3*MD + 6)   // 1542
#define EPSF    1e-16f

// ---- scratch (device globals: no allocation allowed) ----
__device__ float g_o[MD + 6];     // k (512) + 6 scalars
__device__ float g_e[MD];
__device__ float g_a[MD];
__device__ float g_expwc[N_SLOTS];
__device__ float g_wp[N_SLOTS];
__device__ float g_partialB[512];
__device__ float g_partialC[64];

__device__ __forceinline__ float softplusf(float x) {
    return x > 20.f ? x : log1pf(expf(x));
}

// ---- K1: o = emb @ W^T + b (one warp per output row).
//      Rows [0,518) -> g_o ; e rows -> g_e (aligned) ; a rows -> g_a. ----
__global__ void k_proj(const float* __restrict__ emb,
                       const float* __restrict__ W,
                       const float* __restrict__ b) {
    int warp = threadIdx.x >> 5;
    int lane = threadIdx.x & 31;
    int row  = blockIdx.x * 4 + warp;
    if (row >= OUTF) return;
    const float4* W4 = (const float4*)(W + (size_t)row * CTRL);
    const float4* e4 = (const float4*)emb;
    float sum = 0.f;
#pragma unroll
    for (int j = 0; j < 8; j++) {
        float4 wv = W4[lane + 32*j];
        float4 ev = e4[lane + 32*j];
        sum += wv.x*ev.x + wv.y*ev.y + wv.z*ev.z + wv.w*ev.w;
    }
#pragma unroll
    for (int off = 16; off; off >>= 1) sum += __shfl_down_sync(0xffffffffu, sum, off);
    if (lane == 0) {
        float o = sum + b[row];
        if (row < MD + 6)            g_o[row] = o;
        else if (row < 2*MD + 6)     g_e[row - (MD + 6)] = o;
        else                         g_a[row - (2*MD + 6)] = o;
    }
}

// ---- K2: cosine sim + exp(beta*sim). 32 rows/block (2 iterations of
//      2 rows/warp, 8 front-batched LDG.128/thread). Grid 512. ----
__global__ void k_sim(const float* __restrict__ mem) {
    __shared__ float sk[MD];
    __shared__ float sred[32];
    __shared__ float s_beta, s_knorm;
    int tid = threadIdx.x;
    int wid = tid >> 5, lane = tid & 31;

    float ksq = 0.f;
#pragma unroll
    for (int i = tid; i < MD; i += 256) { float v = g_o[i]; sk[i] = v; ksq += v*v; }
#pragma unroll
    for (int off = 16; off; off >>= 1) ksq += __shfl_down_sync(0xffffffffu, ksq, off);
    if (lane == 0) sred[wid] = ksq;
    __syncthreads();
    if (tid == 0) {
        float s = 0.f;
#pragma unroll
        for (int i = 0; i < 8; i++) s += sred[i];
        s_knorm = sqrtf(s);
        s_beta  = softplusf(g_o[MD]);
    }
    __syncthreads();   // sk + s_beta/s_knorm ready

    const float4* k4 = (const float4*)sk;
    float4 kv[4];
#pragma unroll
    for (int q = 0; q < 4; q++) kv[q] = k4[lane + 32*q];

#pragma unroll
    for (int half = 0; half < 2; half++) {
        int row0 = blockIdx.x * 32 + half * 16 + wid;   // rows row0, row0+8
        const float4* mA = (const float4*)(mem + (size_t)row0 * MD);
        const float4* mB = (const float4*)(mem + (size_t)(row0 + 8) * MD);
        float4 va[4], vb[4];
#pragma unroll
        for (int j = 0; j < 4; j++) va[j] = mA[lane + 32*j];
#pragma unroll
        for (int j = 0; j < 4; j++) vb[j] = mB[lane + 32*j];

        float dotA = 0.f, nrmA = 0.f, dotB = 0.f, nrmB = 0.f;
#pragma unroll
        for (int j = 0; j < 4; j++) {
            dotA += va[j].x*kv[j].x + va[j].y*kv[j].y + va[j].z*kv[j].z + va[j].w*kv[j].w;
            nrmA += va[j].x*va[j].x + va[j].y*va[j].y + va[j].z*va[j].z + va[j].w*va[j].w;
            dotB += vb[j].x*kv[j].x + vb[j].y*kv[j].y + vb[j].z*kv[j].z + vb[j].w*kv[j].w;
            nrmB += vb[j].x*vb[j].x + vb[j].y*vb[j].y + vb[j].z*vb[j].z + vb[j].w*vb[j].w;
        }
#pragma unroll
        for (int off = 16; off; off >>= 1) {
            dotA += __shfl_down_sync(0xffffffffu, dotA, off);
            nrmA += __shfl_down_sync(0xffffffffu, nrmA, off);
            dotB += __shfl_down_sync(0xffffffffu, dotB, off);
            nrmB += __shfl_down_sync(0xffffffffu, nrmB, off);
        }
        if (lane == 0) {
            // sim in [-1,1], beta = softplus(~N(0,1)) modest: exp cannot overflow
            float exA = expf(s_beta * dotA / (s_knorm * sqrtf(nrmA) + EPSF));
            float exB = expf(s_beta * dotB / (s_knorm * sqrtf(nrmB) + EPSF));
            g_expwc[row0]     = exA;
            g_expwc[row0 + 8] = exB;
            sred[half * 16 + wid]     = exA;
            sred[half * 16 + wid + 8] = exB;
        }
    }
    __syncthreads();
    if (tid == 0) {
        float s = 0.f;
#pragma unroll
        for (int i = 0; i < 32; i++) s += sred[i];
        g_partialB[blockIdx.x] = s;
    }
}

// ---- K3: interpolate + shift + sharpen. Each block redundantly reduces
//      the 512 exp-partials and derives scalars. 64 blocks x 256. ----
__global__ void k_shiftpow(const float* __restrict__ w_prev) {
    __shared__ float red[256];
    __shared__ float sc[6];   // ise, g, s0, s1, s2, gamma
    int tid = threadIdx.x;

    float s = g_partialB[tid] + g_partialB[tid + 256];
    red[tid] = s;
    __syncthreads();
    for (int st = 128; st; st >>= 1) { if (tid < st) red[tid] += red[tid+st]; __syncthreads(); }
    if (tid == 0) {
        sc[0] = 1.f / red[0];
        sc[1] = 1.f / (1.f + expf(-g_o[MD+1]));
        float x0 = g_o[MD+2], x1 = g_o[MD+3], x2 = g_o[MD+4];
        float m  = fmaxf(x0, fmaxf(x1, x2));
        float e0 = expf(x0-m), e1 = expf(x1-m), e2 = expf(x2-m);
        float inv = 1.f / (e0 + e1 + e2);
        sc[2] = e0*inv; sc[3] = e1*inv; sc[4] = e2*inv;
        sc[5] = 1.f + softplusf(g_o[MD+5]);
    }
    __syncthreads();

    float ise = sc[0], gg = sc[1], s0 = sc[2], s1 = sc[3], s2 = sc[4], gamma = sc[5];
    float omg = 1.f - gg;
    int i = blockIdx.x * 256 + tid;
    int im = (i == 0) ? N_SLOTS-1 : i-1;
    int ip = (i == N_SLOTS-1) ? 0 : i+1;
    float wgm = gg * g_expwc[im] * ise + omg * w_prev[im];
    float wgc = gg * g_expwc[i ] * ise + omg * w_prev[i ];
    float wgp = gg * g_expwc[ip] * ise + omg * w_prev[ip];
    float ws = s0*wgm + s1*wgc + s2*wgp;
    float wp = exp2f(gamma * log2f(ws + EPSF));   // ws+EPS > 0 always
    g_wp[i] = wp;
    red[tid] = wp;
    __syncthreads();
    for (int st = 128; st; st >>= 1) { if (tid < st) red[tid] += red[tid+st]; __syncthreads(); }
    if (tid == 0) g_partialC[blockIdx.x] = red[0];
}

// ---- K4: memory update + w output. Barrier-free; 512-thread blocks,
//      32 rows/block, 8 rows/thread. Grid 512 (~3.5 waves). ----
__global__ void __launch_bounds__(512)
k_update(const float* __restrict__ mem, float* __restrict__ out) {
    int tid  = threadIdx.x;
    int lane = tid & 31;
    int base = blockIdx.x * 32;
    int c    = tid & 127;   // float4 column
    int half = tid >> 7;    // 0..3 (warp-uniform)

    // batch all 8 independent row loads first
    float4 m[8];
#pragma unroll
    for (int it = 0; it < 8; it++) {
        int row = base + half + 4*it;
        m[it] = ((const float4*)(mem + (size_t)row * MD))[c];
    }
    float4 e = ((const float4*)g_e)[c];
    float4 a = ((const float4*)g_a)[c];

    // warp-redundant deterministic reduce of 64 wp-partials (no barriers)
    float s = g_partialC[lane] + g_partialC[lane + 32];
#pragma unroll
    for (int off = 16; off; off >>= 1) s += __shfl_xor_sync(0xffffffffu, s, off);
    float inv = 1.f / s;

    // this warp's 8 row-weights: ONE predicated load, then shfl broadcast
    float wp_l = (lane < 8) ? g_wp[base + half + 4*lane] : 0.f;
    float wv[8];
#pragma unroll
    for (int it = 0; it < 8; it++) wv[it] = __shfl_sync(0xffffffffu, wp_l, it) * inv;

    if (tid < 32) out[base + tid] = g_wp[base + tid] * inv;

    float* nm = out + N_SLOTS;
#pragma unroll
    for (int it = 0; it < 8; it++) {
        int row = base + half + 4*it;
        float4 r;
        r.x = m[it].x * (1.f - wv[it]*e.x) + wv[it]*a.x;
        r.y = m[it].y * (1.f - wv[it]*e.y) + wv[it]*a.y;
        r.z = m[it].z * (1.f - wv[it]*e.z) + wv[it]*a.z;
        r.w = m[it].w * (1.f - wv[it]*e.w) + wv[it]*a.w;
        __stcs((float4*)(nm + (size_t)row * MD) + c, r);   // streaming: never re-read
    }
}

extern "C" void kernel_launch(void* const* d_in, const int* in_sizes, int n_in,
                              void* d_out, int out_size) {
    const float* emb    = (const float*)d_in[0];   // (1, 1024)
    const float* w_prev = (const float*)d_in[1];   // (1, 16384)
    const float* mem    = (const float*)d_in[2];   // (16384, 512)
    const float* W      = (const float*)d_in[3];   // (1542, 1024)
    const float* b      = (const float*)d_in[4];   // (1542,)
    float* out = (float*)d_out;                    // [w(16384) | new_memory(16384*512)]

    k_proj<<<(OUTF + 3) / 4, 128>>>(emb, W, b);
    k_sim<<<N_SLOTS / 32, 256>>>(mem);
    k_shiftpow<<<N_SLOTS / 256, 256>>>(w_prev);
    k_update<<<N_SLOTS / 32, 512>>>(mem, out);
}

// round 13
// speedup vs baseline: 1.2922x; 1.0014x over previous
#include <cuda_runtime.h>
#include <math.h>
#include <stdint.h>

#define N_SLOTS 16384
#define MD      512
#define CTRL    1024
#define OUTF    (3*MD + 6)   // 1542
#define NKROWS  (MD + 6)     // 518: rows needed before k_sim
#define EPSF    1e-16f

// ---- scratch (device globals: no allocation allowed) ----
__device__ float g_o[MD + 6];     // k (512) + 6 scalars
__device__ float g_e[MD];
__device__ float g_a[MD];
__device__ float g_expwc[N_SLOTS];
__device__ float g_wp[N_SLOTS];
__device__ float g_partialB[1024];
__device__ float g_partialC[64];

__device__ __forceinline__ float softplusf(float x) {
    return x > 20.f ? x : log1pf(expf(x));
}

__device__ __forceinline__ float warp_dot_row(const float4* __restrict__ W4,
                                              const float4* __restrict__ e4,
                                              int lane) {
    float sum = 0.f;
#pragma unroll
    for (int j = 0; j < 8; j++) {
        float4 wv = W4[lane + 32*j];
        float4 ev = e4[lane + 32*j];
        sum += wv.x*ev.x + wv.y*ev.y + wv.z*ev.z + wv.w*ev.w;
    }
#pragma unroll
    for (int off = 16; off; off >>= 1) sum += __shfl_down_sync(0xffffffffu, sum, off);
    return sum;
}

// ---- K1: k + scalar rows only (518 rows) -> g_o. One warp per row. ----
__global__ void k_proj(const float* __restrict__ emb,
                       const float* __restrict__ W,
                       const float* __restrict__ b) {
    int warp = threadIdx.x >> 5;
    int lane = threadIdx.x & 31;
    int row  = blockIdx.x * 4 + warp;
    if (row >= NKROWS) return;
    float sum = warp_dot_row((const float4*)(W + (size_t)row * CTRL),
                             (const float4*)emb, lane);
    if (lane == 0) g_o[row] = sum + b[row];
}

// ---- K2: blocks [0,1024): cosine sim + exp(beta*sim), 16 rows/block,
//      2 rows/warp with 8 front-batched LDG.128/thread.
//      blocks [1024,1088): project e/a rows (16 rows/block) concurrently. ----
__global__ void k_sim(const float* __restrict__ mem,
                      const float* __restrict__ emb,
                      const float* __restrict__ W,
                      const float* __restrict__ b) {
    int tid = threadIdx.x;
    int wid = tid >> 5, lane = tid & 31;

    if (blockIdx.x >= 1024) {
        // ---- e/a projection: rows NKROWS + (bid-1024)*16 + [0,16) ----
        int r0 = NKROWS + (blockIdx.x - 1024) * 16;
#pragma unroll
        for (int h = 0; h < 2; h++) {
            int row = r0 + wid * 2 + h;
            float sum = warp_dot_row((const float4*)(W + (size_t)row * CTRL),
                                     (const float4*)emb, lane);
            if (lane == 0) {
                float o = sum + b[row];
                if (row < 2*MD + 6) g_e[row - NKROWS] = o;
                else                g_a[row - (2*MD + 6)] = o;
            }
        }
        return;
    }

    __shared__ float sk[MD];
    __shared__ float sred[16];
    __shared__ float s_beta, s_knorm;

    // front-batch the 8 global row loads (independent of k/smem work)
    int row0 = blockIdx.x * 16 + wid;        // rows row0 and row0+8
    const float4* mA = (const float4*)(mem + (size_t)row0 * MD);
    const float4* mB = (const float4*)(mem + (size_t)(row0 + 8) * MD);
    float4 va[4], vb[4];
#pragma unroll
    for (int j = 0; j < 4; j++) va[j] = mA[lane + 32*j];
#pragma unroll
    for (int j = 0; j < 4; j++) vb[j] = mB[lane + 32*j];

    float ksq = 0.f;
#pragma unroll
    for (int i = tid; i < MD; i += 256) { float v = g_o[i]; sk[i] = v; ksq += v*v; }
#pragma unroll
    for (int off = 16; off; off >>= 1) ksq += __shfl_down_sync(0xffffffffu, ksq, off);
    if (lane == 0) sred[wid] = ksq;
    __syncthreads();
    if (tid == 0) {
        float s = 0.f;
#pragma unroll
        for (int i = 0; i < 8; i++) s += sred[i];
        s_knorm = sqrtf(s);
        s_beta  = softplusf(g_o[MD]);
    }
    __syncthreads();   // sk + s_beta/s_knorm ready

    const float4* k4 = (const float4*)sk;
    float dotA = 0.f, nrmA = 0.f, dotB = 0.f, nrmB = 0.f;
#pragma unroll
    for (int j = 0; j < 4; j++) {
        float4 kv = k4[lane + 32*j];
        dotA += va[j].x*kv.x + va[j].y*kv.y + va[j].z*kv.z + va[j].w*kv.w;
        nrmA += va[j].x*va[j].x + va[j].y*va[j].y + va[j].z*va[j].z + va[j].w*va[j].w;
        dotB += vb[j].x*kv.x + vb[j].y*kv.y + vb[j].z*kv.z + vb[j].w*kv.w;
        nrmB += vb[j].x*vb[j].x + vb[j].y*vb[j].y + vb[j].z*vb[j].z + vb[j].w*vb[j].w;
    }
#pragma unroll
    for (int off = 16; off; off >>= 1) {
        dotA += __shfl_down_sync(0xffffffffu, dotA, off);
        nrmA += __shfl_down_sync(0xffffffffu, nrmA, off);
        dotB += __shfl_down_sync(0xffffffffu, dotB, off);
        nrmB += __shfl_down_sync(0xffffffffu, nrmB, off);
    }
    if (lane == 0) {
        // sim in [-1,1], beta = softplus(~N(0,1)) modest: exp cannot overflow
        float exA = expf(s_beta * dotA / (s_knorm * sqrtf(nrmA) + EPSF));
        float exB = expf(s_beta * dotB / (s_knorm * sqrtf(nrmB) + EPSF));
        g_expwc[row0]     = exA;
        g_expwc[row0 + 8] = exB;
        sred[wid]     = exA;
        sred[wid + 8] = exB;
    }
    __syncthreads();
    if (tid == 0) {
        float s = 0.f;
#pragma unroll
        for (int i = 0; i < 16; i++) s += sred[i];
        g_partialB[blockIdx.x] = s;
    }
}

// ---- K3: interpolate + shift + sharpen. Each block redundantly reduces
//      the 1024 exp-partials and derives scalars. 64 blocks x 256. ----
__global__ void k_shiftpow(const float* __restrict__ w_prev) {
    __shared__ float red[256];
    __shared__ float sc[6];   // ise, g, s0, s1, s2, gamma
    int tid = threadIdx.x;

    float s = 0.f;
#pragma unroll
    for (int j = 0; j < 4; j++) s += g_partialB[tid + 256*j];
    red[tid] = s;
    __syncthreads();
    for (int st = 128; st; st >>= 1) { if (tid < st) red[tid] += red[tid+st]; __syncthreads(); }
    if (tid == 0) {
        sc[0] = 1.f / red[0];
        sc[1] = 1.f / (1.f + expf(-g_o[MD+1]));
        float x0 = g_o[MD+2], x1 = g_o[MD+3], x2 = g_o[MD+4];
        float m  = fmaxf(x0, fmaxf(x1, x2));
        float e0 = expf(x0-m), e1 = expf(x1-m), e2 = expf(x2-m);
        float inv = 1.f / (e0 + e1 + e2);
        sc[2] = e0*inv; sc[3] = e1*inv; sc[4] = e2*inv;
        sc[5] = 1.f + softplusf(g_o[MD+5]);
    }
    __syncthreads();

    float ise = sc[0], gg = sc[1], s0 = sc[2], s1 = sc[3], s2 = sc[4], gamma = sc[5];
    float omg = 1.f - gg;
    int i = blockIdx.x * 256 + tid;
    int im = (i == 0) ? N_SLOTS-1 : i-1;
    int ip = (i == N_SLOTS-1) ? 0 : i+1;
    float wgm = gg * g_expwc[im] * ise + omg * w_prev[im];
    float wgc = gg * g_expwc[i ] * ise + omg * w_prev[i ];
    float wgp = gg * g_expwc[ip] * ise + omg * w_prev[ip];
    float ws = s0*wgm + s1*wgc + s2*wgp;
    float wp = exp2f(gamma * log2f(ws + EPSF));   // ws+EPS > 0 always
    g_wp[i] = wp;
    red[tid] = wp;
    __syncthreads();
    for (int st = 128; st; st >>= 1) { if (tid < st) red[tid] += red[tid+st]; __syncthreads(); }
    if (tid == 0) g_partialC[blockIdx.x] = red[0];
}

// ---- K4: memory update + w output. Barrier-free; 16 rows per 256-thread
//      block, 8 rows/thread (empirical optimum). wp via one predicated
//      load + shfl broadcast. ----
__global__ void k_update(const float* __restrict__ mem, float* __restrict__ out) {
    int tid  = threadIdx.x;
    int lane = tid & 31;
    int base = blockIdx.x * 16;
    int c    = tid & 127;   // float4 column
    int half = tid >> 7;    // 0/1 (warp-uniform)

    // batch all 8 independent row loads first
    float4 m[8];
#pragma unroll
    for (int it = 0; it < 8; it++) {
        int row = base + half + 2*it;
        m[it] = ((const float4*)(mem + (size_t)row * MD))[c];
    }
    float4 e = ((const float4*)g_e)[c];
    float4 a = ((const float4*)g_a)[c];

    // warp-redundant deterministic reduce of 64 wp-partials (no barriers)
    float s = g_partialC[lane] + g_partialC[lane + 32];
#pragma unroll
    for (int off = 16; off; off >>= 1) s += __shfl_xor_sync(0xffffffffu, s, off);
    float inv = 1.f / s;

    // this warp's 8 row-weights: ONE predicated load, then shfl broadcast
    float wp_l = (lane < 8) ? g_wp[base + half + 2*lane] : 0.f;
    float wv[8];
#pragma unroll
    for (int it = 0; it < 8; it++) wv[it] = __shfl_sync(0xffffffffu, wp_l, it) * inv;

    if (tid < 16) out[base + tid] = g_wp[base + tid] * inv;

    float* nm = out + N_SLOTS;
#pragma unroll
    for (int it = 0; it < 8; it++) {
        int row = base + half + 2*it;
        float4 r;
        r.x = m[it].x * (1.f - wv[it]*e.x) + wv[it]*a.x;
        r.y = m[it].y * (1.f - wv[it]*e.y) + wv[it]*a.y;
        r.z = m[it].z * (1.f - wv[it]*e.z) + wv[it]*a.z;
        r.w = m[it].w * (1.f - wv[it]*e.w) + wv[it]*a.w;
        __stcs((float4*)(nm + (size_t)row * MD) + c, r);   // streaming: never re-read
    }
}

extern "C" void kernel_launch(void* const* d_in, const int* in_sizes, int n_in,
                              void* d_out, int out_size) {
    const float* emb    = (const float*)d_in[0];   // (1, 1024)
    const float* w_prev = (const float*)d_in[1];   // (1, 16384)
    const float* mem    = (const float*)d_in[2];   // (16384, 512)
    const float* W      = (const float*)d_in[3];   // (1542, 1024)
    const float* b      = (const float*)d_in[4];   // (1542,)
    float* out = (float*)d_out;                    // [w(16384) | new_memory(16384*512)]

    k_proj<<<(NKROWS + 3) / 4, 128>>>(emb, W, b);
    k_sim<<<1024 + 64, 256>>>(mem, emb, W, b);
    k_shiftpow<<<64, 256>>>(w_prev);
    k_update<<<N_SLOTS / 16, 256>>>(mem, out);
}

// round 14
// speedup vs baseline: 1.3908x; 1.0763x over previous
#include <cuda_runtime.h>
#include <math.h>
#include <stdint.h>

#define N_SLOTS 16384
#define MD      512
#define CTRL    1024
#define OUTF    (3*MD + 6)   // 1542
#define NKROWS  (MD + 6)     // 518: rows needed before k_sim
#define EPSF    1e-16f

// ---- scratch (device globals: no allocation allowed) ----
__device__ float g_o[MD + 6];     // k (512) + 6 scalars
__device__ float g_e[MD];
__device__ float g_a[MD];
__device__ float g_expwc[N_SLOTS];
__device__ float g_wp[N_SLOTS];
__device__ float g_partialB[1024];
__device__ float g_partialC[64];

__device__ __forceinline__ float softplusf(float x) {
    return x > 20.f ? x : log1pf(__expf(x));
}

__device__ __forceinline__ float warp_dot_row(const float4* __restrict__ W4,
                                              const float4* __restrict__ e4,
                                              int lane) {
    float sum = 0.f;
#pragma unroll
    for (int j = 0; j < 8; j++) {
        float4 wv = W4[lane + 32*j];
        float4 ev = e4[lane + 32*j];
        sum += wv.x*ev.x + wv.y*ev.y + wv.z*ev.z + wv.w*ev.w;
    }
#pragma unroll
    for (int off = 16; off; off >>= 1) sum += __shfl_down_sync(0xffffffffu, sum, off);
    return sum;
}

// ---- K1: k + scalar rows only (518 rows) -> g_o. One warp per row. ----
__global__ void k_proj(const float* __restrict__ emb,
                       const float* __restrict__ W,
                       const float* __restrict__ b) {
    int warp = threadIdx.x >> 5;
    int lane = threadIdx.x & 31;
    int row  = blockIdx.x * 4 + warp;
    if (row >= NKROWS) return;
    float sum = warp_dot_row((const float4*)(W + (size_t)row * CTRL),
                             (const float4*)emb, lane);
    if (lane == 0) g_o[row] = sum + b[row];
}

// ---- K2: blocks [0,64): project e/a rows (16 rows/block) — FIRST so they
//      launch in wave 1 and hide under the sim DRAM stream.
//      blocks [64,1088): cosine sim + exp(beta*sim), 16 rows/block,
//      2 rows/warp with 8 front-batched LDG.128/thread. ----
__global__ void k_sim(const float* __restrict__ mem,
                      const float* __restrict__ emb,
                      const float* __restrict__ W,
                      const float* __restrict__ b) {
    int tid = threadIdx.x;
    int wid = tid >> 5, lane = tid & 31;

    if (blockIdx.x < 64) {
        // ---- e/a projection: rows NKROWS + bid*16 + [0,16) ----
        int r0 = NKROWS + blockIdx.x * 16;
#pragma unroll
        for (int h = 0; h < 2; h++) {
            int row = r0 + wid * 2 + h;
            float sum = warp_dot_row((const float4*)(W + (size_t)row * CTRL),
                                     (const float4*)emb, lane);
            if (lane == 0) {
                float o = sum + b[row];
                if (row < 2*MD + 6) g_e[row - NKROWS] = o;
                else                g_a[row - (2*MD + 6)] = o;
            }
        }
        return;
    }
    int sbid = blockIdx.x - 64;   // 0..1023

    __shared__ float sk[MD];
    __shared__ float sred[16];
    __shared__ float s_beta, s_knorm;

    // front-batch the 8 global row loads (independent of k/smem work)
    int row0 = sbid * 16 + wid;        // rows row0 and row0+8
    const float4* mA = (const float4*)(mem + (size_t)row0 * MD);
    const float4* mB = (const float4*)(mem + (size_t)(row0 + 8) * MD);
    float4 va[4], vb[4];
#pragma unroll
    for (int j = 0; j < 4; j++) va[j] = mA[lane + 32*j];
#pragma unroll
    for (int j = 0; j < 4; j++) vb[j] = mB[lane + 32*j];

    float ksq = 0.f;
#pragma unroll
    for (int i = tid; i < MD; i += 256) { float v = g_o[i]; sk[i] = v; ksq += v*v; }
#pragma unroll
    for (int off = 16; off; off >>= 1) ksq += __shfl_down_sync(0xffffffffu, ksq, off);
    if (lane == 0) sred[wid] = ksq;
    __syncthreads();
    if (tid == 0) {
        float s = 0.f;
#pragma unroll
        for (int i = 0; i < 8; i++) s += sred[i];
        s_knorm = sqrtf(s);
        s_beta  = softplusf(g_o[MD]);
    }
    __syncthreads();   // sk + s_beta/s_knorm ready

    const float4* k4 = (const float4*)sk;
    float dotA = 0.f, nrmA = 0.f, dotB = 0.f, nrmB = 0.f;
#pragma unroll
    for (int j = 0; j < 4; j++) {
        float4 kv = k4[lane + 32*j];
        dotA += va[j].x*kv.x + va[j].y*kv.y + va[j].z*kv.z + va[j].w*kv.w;
        nrmA += va[j].x*va[j].x + va[j].y*va[j].y + va[j].z*va[j].z + va[j].w*va[j].w;
        dotB += vb[j].x*kv.x + vb[j].y*kv.y + vb[j].z*kv.z + vb[j].w*kv.w;
        nrmB += vb[j].x*vb[j].x + vb[j].y*vb[j].y + vb[j].z*vb[j].z + vb[j].w*vb[j].w;
    }
#pragma unroll
    for (int off = 16; off; off >>= 1) {
        dotA += __shfl_down_sync(0xffffffffu, dotA, off);
        nrmA += __shfl_down_sync(0xffffffffu, nrmA, off);
        dotB += __shfl_down_sync(0xffffffffu, dotB, off);
        nrmB += __shfl_down_sync(0xffffffffu, nrmB, off);
    }
    if (lane == 0) {
        // sim in [-1,1], beta = softplus(~N(0,1)) modest: exp cannot overflow
        float exA = __expf(s_beta * dotA / (s_knorm * sqrtf(nrmA) + EPSF));
        float exB = __expf(s_beta * dotB / (s_knorm * sqrtf(nrmB) + EPSF));
        g_expwc[row0]     = exA;
        g_expwc[row0 + 8] = exB;
        sred[wid]     = exA;
        sred[wid + 8] = exB;
    }
    __syncthreads();
    if (tid == 0) {
        float s = 0.f;
#pragma unroll
        for (int i = 0; i < 16; i++) s += sred[i];
        g_partialB[sbid] = s;
    }
}

// ---- K3: interpolate + shift + sharpen. Each block redundantly reduces
//      the 1024 exp-partials and derives scalars. 64 blocks x 256. ----
__global__ void k_shiftpow(const float* __restrict__ w_prev) {
    __shared__ float red[256];
    __shared__ float sc[6];   // ise, g, s0, s1, s2, gamma
    int tid = threadIdx.x;

    float s = 0.f;
#pragma unroll
    for (int j = 0; j < 4; j++) s += g_partialB[tid + 256*j];
    red[tid] = s;
    __syncthreads();
    for (int st = 128; st; st >>= 1) { if (tid < st) red[tid] += red[tid+st]; __syncthreads(); }
    if (tid == 0) {
        sc[0] = 1.f / red[0];
        sc[1] = 1.f / (1.f + __expf(-g_o[MD+1]));
        float x0 = g_o[MD+2], x1 = g_o[MD+3], x2 = g_o[MD+4];
        float m  = fmaxf(x0, fmaxf(x1, x2));
        float e0 = __expf(x0-m), e1 = __expf(x1-m), e2 = __expf(x2-m);
        float inv = 1.f / (e0 + e1 + e2);
        sc[2] = e0*inv; sc[3] = e1*inv; sc[4] = e2*inv;
        sc[5] = 1.f + softplusf(g_o[MD+5]);
    }
    __syncthreads();

    float ise = sc[0], gg = sc[1], s0 = sc[2], s1 = sc[3], s2 = sc[4], gamma = sc[5];
    float omg = 1.f - gg;
    int i = blockIdx.x * 256 + tid;
    int im = (i == 0) ? N_SLOTS-1 : i-1;
    int ip = (i == N_SLOTS-1) ? 0 : i+1;
    float wgm = gg * g_expwc[im] * ise + omg * w_prev[im];
    float wgc = gg * g_expwc[i ] * ise + omg * w_prev[i ];
    float wgp = gg * g_expwc[ip] * ise + omg * w_prev[ip];
    float ws = s0*wgm + s1*wgc + s2*wgp;
    float wp = exp2f(gamma * __log2f(ws + EPSF));   // ws+EPS > 0 always
    g_wp[i] = wp;
    red[tid] = wp;
    __syncthreads();
    for (int st = 128; st; st >>= 1) { if (tid < st) red[tid] += red[tid+st]; __syncthreads(); }
    if (tid == 0) g_partialC[blockIdx.x] = red[0];
}

// ---- K4: memory update + w output. Barrier-free; 16 rows per 256-thread
//      block, 8 rows/thread (empirical optimum). wp via one predicated
//      load + shfl broadcast. ----
__global__ void k_update(const float* __restrict__ mem, float* __restrict__ out) {
    int tid  = threadIdx.x;
    int lane = tid & 31;
    int base = blockIdx.x * 16;
    int c    = tid & 127;   // float4 column
    int half = tid >> 7;    // 0/1 (warp-uniform)

    // batch all 8 independent row loads first
    float4 m[8];
#pragma unroll
    for (int it = 0; it < 8; it++) {
        int row = base + half + 2*it;
        m[it] = ((const float4*)(mem + (size_t)row * MD))[c];
    }
    float4 e = ((const float4*)g_e)[c];
    float4 a = ((const float4*)g_a)[c];

    // warp-redundant deterministic reduce of 64 wp-partials (no barriers)
    float s = g_partialC[lane] + g_partialC[lane + 32];
#pragma unroll
    for (int off = 16; off; off >>= 1) s += __shfl_xor_sync(0xffffffffu, s, off);
    float inv = 1.f / s;

    // this warp's 8 row-weights: ONE predicated load, then shfl broadcast
    float wp_l = (lane < 8) ? g_wp[base + half + 2*lane] : 0.f;
    float wv[8];
#pragma unroll
    for (int it = 0; it < 8; it++) wv[it] = __shfl_sync(0xffffffffu, wp_l, it) * inv;

    if (tid < 16) out[base + tid] = g_wp[base + tid] * inv;

    float* nm = out + N_SLOTS;
#pragma unroll
    for (int it = 0; it < 8; it++) {
        int row = base + half + 2*it;
        float4 r;
        r.x = m[it].x * (1.f - wv[it]*e.x) + wv[it]*a.x;
        r.y = m[it].y * (1.f - wv[it]*e.y) + wv[it]*a.y;
        r.z = m[it].z * (1.f - wv[it]*e.z) + wv[it]*a.z;
        r.w = m[it].w * (1.f - wv[it]*e.w) + wv[it]*a.w;
        __stcs((float4*)(nm + (size_t)row * MD) + c, r);   // streaming: never re-read
    }
}

extern "C" void kernel_launch(void* const* d_in, const int* in_sizes, int n_in,
                              void* d_out, int out_size) {
    const float* emb    = (const float*)d_in[0];   // (1, 1024)
    const float* w_prev = (const float*)d_in[1];   // (1, 16384)
    const float* mem    = (const float*)d_in[2];   // (16384, 512)
    const float* W      = (const float*)d_in[3];   // (1542, 1024)
    const float* b      = (const float*)d_in[4];   // (1542,)
    float* out = (float*)d_out;                    // [w(16384) | new_memory(16384*512)]

    k_proj<<<(NKROWS + 3) / 4, 128>>>(emb, W, b);
    k_sim<<<64 + 1024, 256>>>(mem, emb, W, b);
    k_shiftpow<<<64, 256>>>(w_prev);
    k_update<<<N_SLOTS / 16, 256>>>(mem, out);
}